// round 1
// baseline (speedup 1.0000x reference)
#include <cuda_runtime.h>
#include <cuda_bf16.h>
#include <math.h>

// Problem constants
#define HWDIM 80          // H == W == 80
#define NPIX  6400        // 80*80
#define DIM   512
#define QKVN  1536        // 3*DIM
#define NHEAD 8
#define HD    64
#define KWIN  7

// Scratch (allocation-free rule: __device__ globals)
__device__ float g_qkv[(size_t)NPIX * QKVN];   // [pix][3*8*64]
__device__ float g_att[(size_t)NPIX * DIM];    // [pix][head*64+d]

// ---------------------------------------------------------------------------
// SGEMM: C[M,N] = A[M,K] * B[N,K]^T + bias[N]
// A row-major [M,K], B row-major [N,K] (i.e. NT layout, both K-contiguous).
// 128x128 tile, BK=16, 256 threads, 8x8 microtile (split 4+4 at +64 offsets).
// M % 128 == 0, N % 128 == 0, K % 16 == 0 hold for all call sites here.
// ---------------------------------------------------------------------------
__global__ void __launch_bounds__(256) sgemm_nt_bias(
    const float* __restrict__ A, const float* __restrict__ B,
    const float* __restrict__ bias, float* __restrict__ C,
    int M, int N, int K)
{
    __shared__ float As[16][128];
    __shared__ float Bs[16][128];

    const int tid = threadIdx.x;
    const int bm = blockIdx.y * 128;
    const int bn = blockIdx.x * 128;
    const int tx = tid & 15;
    const int ty = tid >> 4;
    const int r0 = ty * 4;
    const int c0 = tx * 4;

    float acc[8][8];
#pragma unroll
    for (int x = 0; x < 8; x++)
#pragma unroll
        for (int y = 0; y < 8; y++) acc[x][y] = 0.f;

    for (int k0 = 0; k0 < K; k0 += 16) {
        // Load 128x16 tiles of A and B (transposed into smem: [k][m])
#pragma unroll
        for (int l = 0; l < 2; l++) {
            int f = tid + l * 256;      // 0..511 -> 512 float4 per tile
            int r = f >> 2;             // 0..127 tile row
            int c = (f & 3) * 4;        // k offset 0,4,8,12
            float4 va = *(const float4*)(A + (size_t)(bm + r) * K + k0 + c);
            As[c + 0][r] = va.x; As[c + 1][r] = va.y;
            As[c + 2][r] = va.z; As[c + 3][r] = va.w;
            float4 vb = *(const float4*)(B + (size_t)(bn + r) * K + k0 + c);
            Bs[c + 0][r] = vb.x; Bs[c + 1][r] = vb.y;
            Bs[c + 2][r] = vb.z; Bs[c + 3][r] = vb.w;
        }
        __syncthreads();

#pragma unroll
        for (int kk = 0; kk < 16; kk++) {
            float4 a0 = *(const float4*)&As[kk][r0];
            float4 a1 = *(const float4*)&As[kk][r0 + 64];
            float4 b0 = *(const float4*)&Bs[kk][c0];
            float4 b1 = *(const float4*)&Bs[kk][c0 + 64];
            float af[8] = {a0.x, a0.y, a0.z, a0.w, a1.x, a1.y, a1.z, a1.w};
            float bf[8] = {b0.x, b0.y, b0.z, b0.w, b1.x, b1.y, b1.z, b1.w};
#pragma unroll
            for (int x = 0; x < 8; x++)
#pragma unroll
                for (int y = 0; y < 8; y++)
                    acc[x][y] = fmaf(af[x], bf[y], acc[x][y]);
        }
        __syncthreads();
    }

    // Epilogue: add bias, float4 stores
#pragma unroll
    for (int xg = 0; xg < 2; xg++) {
#pragma unroll
        for (int x = 0; x < 4; x++) {
            int row = bm + xg * 64 + r0 + x;
#pragma unroll
            for (int yg = 0; yg < 2; yg++) {
                int col = bn + yg * 64 + c0;
                float4 bv = *(const float4*)(bias + col);
                float4 o;
                o.x = acc[xg * 4 + x][yg * 4 + 0] + bv.x;
                o.y = acc[xg * 4 + x][yg * 4 + 1] + bv.y;
                o.z = acc[xg * 4 + x][yg * 4 + 2] + bv.z;
                o.w = acc[xg * 4 + x][yg * 4 + 3] + bv.w;
                *(float4*)(C + (size_t)row * N + col) = o;
            }
        }
    }
}

// ---------------------------------------------------------------------------
// Neighborhood attention: one warp per (pixel, head).
// Block = 8 warps = 8 adjacent pixels along W, one head (L1 reuse of k/v window).
// Grid = (80/8, 80, 8).
// qkv layout per pixel: [q(512) | k(512) | v(512)], each 512 = head*64 + d.
// ---------------------------------------------------------------------------
__global__ void __launch_bounds__(256) nat_attn(
    const float* __restrict__ qkv, const float* __restrict__ rpb,
    float* __restrict__ att)
{
    const int warp = threadIdx.x >> 5;
    const int lane = threadIdx.x & 31;
    const int j = blockIdx.x * 8 + warp;   // W coordinate
    const int i = blockIdx.y;              // H coordinate
    const int h = blockIdx.z;              // head
    const int pix = i * HWDIM + j;

    // clipped window starts
    const int sh = min(max(i - 3, 0), HWDIM - KWIN);
    const int sw = min(max(j - 3, 0), HWDIM - KWIN);

    // q (scaled): 2 dims per lane
    const float2 qv = ((const float2*)(qkv + (size_t)pix * QKVN + h * HD))[lane];
    const float qx = qv.x * 0.125f;   // 64^-0.5
    const float qy = qv.y * 0.125f;

    // rpb base for this pixel: rpb[h, sh-i+6+a, sw-j+6+c]
    const float* rp = rpb + h * 169 + (sh - i + 6) * 13 + (sw - j + 6);

    float loc0 = -1e30f, loc1 = -1e30f;   // scores owned per lane (t and t+32)

#pragma unroll
    for (int a = 0; a < KWIN; a++) {
        const float* kbase = qkv + (size_t)((sh + a) * HWDIM + sw) * QKVN + DIM + h * HD;
#pragma unroll
        for (int c = 0; c < KWIN; c++) {
            float2 kv = ((const float2*)(kbase + (size_t)c * QKVN))[lane];
            float s = qx * kv.x + qy * kv.y;
#pragma unroll
            for (int o = 16; o; o >>= 1)
                s += __shfl_xor_sync(0xffffffffu, s, o);
            s += rp[a * 13 + c];
            const int t = a * KWIN + c;
            if ((t & 31) == lane) {
                if (t < 32) loc0 = s; else loc1 = s;
            }
        }
    }

    // softmax over 49 scores distributed across lanes
    float m = fmaxf(loc0, loc1);
#pragma unroll
    for (int o = 16; o; o >>= 1)
        m = fmaxf(m, __shfl_xor_sync(0xffffffffu, m, o));
    float e0 = __expf(loc0 - m);
    float e1 = __expf(loc1 - m);
    float sum = e0 + e1;
#pragma unroll
    for (int o = 16; o; o >>= 1)
        sum += __shfl_xor_sync(0xffffffffu, sum, o);
    const float inv = __fdividef(1.f, sum);
    e0 *= inv;
    e1 *= inv;

    // out = sum_t a_t * v_t
    float accx = 0.f, accy = 0.f;
#pragma unroll
    for (int a = 0; a < KWIN; a++) {
        const float* vbase = qkv + (size_t)((sh + a) * HWDIM + sw) * QKVN + 2 * DIM + h * HD;
#pragma unroll
        for (int c = 0; c < KWIN; c++) {
            const int t = a * KWIN + c;
            float at = __shfl_sync(0xffffffffu, (t < 32) ? e0 : e1, t & 31);
            float2 vv = ((const float2*)(vbase + (size_t)c * QKVN))[lane];
            accx = fmaf(at, vv.x, accx);
            accy = fmaf(at, vv.y, accy);
        }
    }

    float2 o2; o2.x = accx; o2.y = accy;
    ((float2*)(att + (size_t)pix * DIM + h * HD))[lane] = o2;
}

// ---------------------------------------------------------------------------
extern "C" void kernel_launch(void* const* d_in, const int* in_sizes, int n_in,
                              void* d_out, int out_size)
{
    const float* x      = (const float*)d_in[0];  // [6400, 512]
    const float* qkv_w  = (const float*)d_in[1];  // [1536, 512]
    const float* qkv_b  = (const float*)d_in[2];  // [1536]
    const float* rpb    = (const float*)d_in[3];  // [8, 13, 13]
    const float* proj_w = (const float*)d_in[4];  // [512, 512]
    const float* proj_b = (const float*)d_in[5];  // [512]
    float* out = (float*)d_out;                   // [6400, 512]

    float *qkv, *att;
    cudaGetSymbolAddress((void**)&qkv, g_qkv);
    cudaGetSymbolAddress((void**)&att, g_att);

    // 1) QKV projection: [6400,1536] = x @ qkv_w^T + qkv_b
    sgemm_nt_bias<<<dim3(QKVN / 128, NPIX / 128), 256>>>(
        x, qkv_w, qkv_b, qkv, NPIX, QKVN, DIM);

    // 2) Neighborhood attention
    nat_attn<<<dim3(HWDIM / 8, HWDIM, NHEAD), 256>>>(qkv, rpb, att);

    // 3) Output projection: [6400,512] = att @ proj_w^T + proj_b
    sgemm_nt_bias<<<dim3(DIM / 128, NPIX / 128), 256>>>(
        att, proj_w, proj_b, out, NPIX, DIM, DIM);
}

// round 3
// speedup vs baseline: 1.7018x; 1.7018x over previous
#include <cuda_runtime.h>
#include <cuda_bf16.h>
#include <cstdint>
#include <math.h>

// Problem constants
#define HWDIM 80
#define NPIX  6400
#define DIM   512
#define QKVN  1536
#define NHEAD 8
#define HD    64
#define KWIN  7

// Scratch (allocation-free rule: __device__ globals)
__device__ float g_qkv[(size_t)NPIX * QKVN];
__device__ float g_att[(size_t)NPIX * DIM];
__device__ __nv_bfloat16 g_xhi[(size_t)NPIX * DIM];
__device__ __nv_bfloat16 g_xlo[(size_t)NPIX * DIM];
__device__ __nv_bfloat16 g_w1hi[(size_t)QKVN * DIM];
__device__ __nv_bfloat16 g_w1lo[(size_t)QKVN * DIM];
__device__ __nv_bfloat16 g_ahi[(size_t)NPIX * DIM];
__device__ __nv_bfloat16 g_alo[(size_t)NPIX * DIM];
__device__ __nv_bfloat16 g_w2hi[(size_t)DIM * DIM];
__device__ __nv_bfloat16 g_w2lo[(size_t)DIM * DIM];

// ---------------------------------------------------------------------------
// fp32 -> bf16 hi/lo split (elementwise). n must be a multiple of 1024.
// ---------------------------------------------------------------------------
__global__ void __launch_bounds__(256) cvt_hilo(
    const float* __restrict__ src,
    __nv_bfloat16* __restrict__ hi, __nv_bfloat16* __restrict__ lo)
{
    const int i = (blockIdx.x * 256 + threadIdx.x) * 4;
    float4 v = *(const float4*)(src + i);
    float f[4] = {v.x, v.y, v.z, v.w};
    __nv_bfloat16 h[4], l[4];
#pragma unroll
    for (int k = 0; k < 4; k++) {
        h[k] = __float2bfloat16(f[k]);
        l[k] = __float2bfloat16(f[k] - __bfloat162float(h[k]));
    }
    uint2 ph, pl;
    {
        __nv_bfloat162 t;
        t = __nv_bfloat162(h[0], h[1]); ph.x = *(uint32_t*)&t;
        t = __nv_bfloat162(h[2], h[3]); ph.y = *(uint32_t*)&t;
        t = __nv_bfloat162(l[0], l[1]); pl.x = *(uint32_t*)&t;
        t = __nv_bfloat162(l[2], l[3]); pl.y = *(uint32_t*)&t;
    }
    *(uint2*)(hi + i) = ph;
    *(uint2*)(lo + i) = pl;
}

// ---------------------------------------------------------------------------
// mma.sync bf16 GEMM (3xBF16 compensated): C[M,N] = A[M,K] @ B[N,K]^T + bias
// A/B given as bf16 hi/lo pairs. 128x128 CTA tile, BK=32, cp.async double buf.
// 256 threads = 8 warps in 2(m) x 4(n); warp tile 64x32.
// ---------------------------------------------------------------------------
#define BK 32
#define ROWB 80                 // padded row stride in bytes (32 bf16 + 8 pad)
#define MATB (128 * ROWB)       // 10240 B per matrix tile
#define STAGEB (4 * MATB)       // Ahi, Alo, Bhi, Blo
#define GEMM_SMEM (2 * STAGEB)  // 81920 B

__device__ __forceinline__ uint32_t smem_u32(const void* p) {
    uint32_t a;
    asm("{ .reg .u64 t; cvta.to.shared.u64 t, %1; cvt.u32.u64 %0, t; }"
        : "=r"(a) : "l"(p));
    return a;
}
__device__ __forceinline__ void cp16(uint32_t dst, const void* src) {
    asm volatile("cp.async.cg.shared.global [%0], [%1], 16;"
                 :: "r"(dst), "l"(src));
}
__device__ __forceinline__ void cp_commit() {
    asm volatile("cp.async.commit_group;" ::: "memory");
}
__device__ __forceinline__ void cp_wait1() {
    asm volatile("cp.async.wait_group 1;" ::: "memory");
}
__device__ __forceinline__ void ldmx4(uint32_t* r, uint32_t addr) {
    asm volatile("ldmatrix.sync.aligned.m8n8.x4.shared.b16 {%0,%1,%2,%3}, [%4];"
                 : "=r"(r[0]), "=r"(r[1]), "=r"(r[2]), "=r"(r[3]) : "r"(addr));
}
__device__ __forceinline__ void ldmx2(uint32_t* r, uint32_t addr) {
    asm volatile("ldmatrix.sync.aligned.m8n8.x2.shared.b16 {%0,%1}, [%2];"
                 : "=r"(r[0]), "=r"(r[1]) : "r"(addr));
}
__device__ __forceinline__ void mma_bf16(float* c, const uint32_t* a, const uint32_t* b) {
    asm volatile(
        "mma.sync.aligned.m16n8k16.row.col.f32.bf16.bf16.f32 "
        "{%0,%1,%2,%3}, {%4,%5,%6,%7}, {%8,%9}, {%0,%1,%2,%3};"
        : "+f"(c[0]), "+f"(c[1]), "+f"(c[2]), "+f"(c[3])
        : "r"(a[0]), "r"(a[1]), "r"(a[2]), "r"(a[3]), "r"(b[0]), "r"(b[1]));
}

__global__ void __launch_bounds__(256, 2) gemm_bf16x3(
    const __nv_bfloat16* __restrict__ Ahi, const __nv_bfloat16* __restrict__ Alo,
    const __nv_bfloat16* __restrict__ Bhi, const __nv_bfloat16* __restrict__ Blo,
    const float* __restrict__ bias, float* __restrict__ C,
    int M, int N, int K)
{
    extern __shared__ char smem[];
    const uint32_t sb = smem_u32(smem);
    const int tid = threadIdx.x;
    const int wid = tid >> 5;
    const int lane = tid & 31;
    const int bm = blockIdx.y * 128;
    const int bn = blockIdx.x * 128;
    const int wm = (wid & 1) * 64;   // warp m offset in tile
    const int wn = (wid >> 1) * 32;  // warp n offset in tile

    const __nv_bfloat16* gb[4] = {Ahi + (size_t)bm * K, Alo + (size_t)bm * K,
                                  Bhi + (size_t)bn * K, Blo + (size_t)bn * K};

    float acc[4][4][4];
#pragma unroll
    for (int mi = 0; mi < 4; mi++)
#pragma unroll
        for (int ni = 0; ni < 4; ni++)
#pragma unroll
            for (int e = 0; e < 4; e++) acc[mi][ni][e] = 0.f;

    const int nch = K / BK;
    const int row = tid >> 2;      // 0..63
    const int chunk = tid & 3;

    // ---- stage loader: 2048 x 16B per stage, 8 per thread ----
    auto load_stage = [&](int buf, int k0) {
#pragma unroll
        for (int it = 0; it < 8; it++) {
            const int mat = it >> 1;                 // compile-time per iter
            const int r = ((it & 1) << 6) + row;     // 0..127
            const __nv_bfloat16* src = gb[mat] + (size_t)r * K + k0 + chunk * 8;
            const uint32_t dst = sb + buf * STAGEB + mat * MATB + r * ROWB + chunk * 16;
            cp16(dst, src);
        }
    };

    load_stage(0, 0);
    cp_commit();

    for (int ch = 0; ch < nch; ch++) {
        if (ch + 1 < nch) load_stage((ch + 1) & 1, (ch + 1) * BK);
        cp_commit();
        cp_wait1();
        __syncthreads();

        const uint32_t st = sb + (ch & 1) * STAGEB;
#pragma unroll
        for (int kk = 0; kk < 2; kk++) {
            // B fragments for all 4 ni (hi & lo)
            uint32_t bh[4][2], bl[4][2];
            const uint32_t boff = (uint32_t)((wn + (lane & 7)) * ROWB
                                  + (kk * 16 + ((lane >> 3) & 1) * 8) * 2);
#pragma unroll
            for (int ni = 0; ni < 4; ni++) {
                ldmx2(bh[ni], st + 2 * MATB + boff + ni * 8 * ROWB);
                ldmx2(bl[ni], st + 3 * MATB + boff + ni * 8 * ROWB);
            }
            const uint32_t aoff = (uint32_t)((wm + (lane & 15)) * ROWB
                                  + (kk * 16 + (lane >> 4) * 8) * 2);
#pragma unroll
            for (int mi = 0; mi < 4; mi++) {
                uint32_t ah[4], al[4];
                ldmx4(ah, st + aoff + mi * 16 * ROWB);
                ldmx4(al, st + MATB + aoff + mi * 16 * ROWB);
#pragma unroll
                for (int ni = 0; ni < 4; ni++) {
                    mma_bf16(acc[mi][ni], ah, bh[ni]);
                    mma_bf16(acc[mi][ni], ah, bl[ni]);
                    mma_bf16(acc[mi][ni], al, bh[ni]);
                }
            }
        }
        __syncthreads();
    }

    // Epilogue: fragment layout m16n8 -> c0,c1 at (g, tg*2..+1), c2,c3 at (g+8)
    const int g = lane >> 2;
    const int tg = lane & 3;
#pragma unroll
    for (int mi = 0; mi < 4; mi++) {
        const int r0 = bm + wm + mi * 16 + g;
#pragma unroll
        for (int ni = 0; ni < 4; ni++) {
            const int col = bn + wn + ni * 8 + tg * 2;
            const float2 bv = *(const float2*)(bias + col);
            float2 o0, o1;
            o0.x = acc[mi][ni][0] + bv.x; o0.y = acc[mi][ni][1] + bv.y;
            o1.x = acc[mi][ni][2] + bv.x; o1.y = acc[mi][ni][3] + bv.y;
            *(float2*)(C + (size_t)r0 * N + col) = o0;
            *(float2*)(C + (size_t)(r0 + 8) * N + col) = o1;
        }
    }
}

// ---------------------------------------------------------------------------
// Neighborhood attention: one warp per (pixel, head).
// ---------------------------------------------------------------------------
__global__ void __launch_bounds__(256) nat_attn(
    const float* __restrict__ qkv, const float* __restrict__ rpb,
    float* __restrict__ att)
{
    const int warp = threadIdx.x >> 5;
    const int lane = threadIdx.x & 31;
    const int j = blockIdx.x * 8 + warp;
    const int i = blockIdx.y;
    const int h = blockIdx.z;
    const int pix = i * HWDIM + j;

    const int sh = min(max(i - 3, 0), HWDIM - KWIN);
    const int sw = min(max(j - 3, 0), HWDIM - KWIN);

    const float2 qv = ((const float2*)(qkv + (size_t)pix * QKVN + h * HD))[lane];
    const float qx = qv.x * 0.125f;
    const float qy = qv.y * 0.125f;

    const float* rp = rpb + h * 169 + (sh - i + 6) * 13 + (sw - j + 6);

    float loc0 = -1e30f, loc1 = -1e30f;

#pragma unroll
    for (int a = 0; a < KWIN; a++) {
        const float* kbase = qkv + (size_t)((sh + a) * HWDIM + sw) * QKVN + DIM + h * HD;
#pragma unroll
        for (int c = 0; c < KWIN; c++) {
            float2 kv = ((const float2*)(kbase + (size_t)c * QKVN))[lane];
            float s = qx * kv.x + qy * kv.y;
#pragma unroll
            for (int o = 16; o; o >>= 1)
                s += __shfl_xor_sync(0xffffffffu, s, o);
            s += rp[a * 13 + c];
            const int t = a * KWIN + c;
            if ((t & 31) == lane) {
                if (t < 32) loc0 = s; else loc1 = s;
            }
        }
    }

    float m = fmaxf(loc0, loc1);
#pragma unroll
    for (int o = 16; o; o >>= 1)
        m = fmaxf(m, __shfl_xor_sync(0xffffffffu, m, o));
    float e0 = __expf(loc0 - m);
    float e1 = __expf(loc1 - m);
    float sum = e0 + e1;
#pragma unroll
    for (int o = 16; o; o >>= 1)
        sum += __shfl_xor_sync(0xffffffffu, sum, o);
    const float inv = __fdividef(1.f, sum);
    e0 *= inv;
    e1 *= inv;

    float accx = 0.f, accy = 0.f;
#pragma unroll
    for (int a = 0; a < KWIN; a++) {
        const float* vbase = qkv + (size_t)((sh + a) * HWDIM + sw) * QKVN + 2 * DIM + h * HD;
#pragma unroll
        for (int c = 0; c < KWIN; c++) {
            const int t = a * KWIN + c;
            float at = __shfl_sync(0xffffffffu, (t < 32) ? e0 : e1, t & 31);
            float2 vv = ((const float2*)(vbase + (size_t)c * QKVN))[lane];
            accx = fmaf(at, vv.x, accx);
            accy = fmaf(at, vv.y, accy);
        }
    }

    float2 o2; o2.x = accx; o2.y = accy;
    ((float2*)(att + (size_t)pix * DIM + h * HD))[lane] = o2;
}

// ---------------------------------------------------------------------------
extern "C" void kernel_launch(void* const* d_in, const int* in_sizes, int n_in,
                              void* d_out, int out_size)
{
    const float* x      = (const float*)d_in[0];
    const float* qkv_w  = (const float*)d_in[1];
    const float* qkv_b  = (const float*)d_in[2];
    const float* rpb    = (const float*)d_in[3];
    const float* proj_w = (const float*)d_in[4];
    const float* proj_b = (const float*)d_in[5];
    float* out = (float*)d_out;

    float *qkv, *att;
    __nv_bfloat16 *xhi, *xlo, *w1hi, *w1lo, *ahi, *alo, *w2hi, *w2lo;
    cudaGetSymbolAddress((void**)&qkv, g_qkv);
    cudaGetSymbolAddress((void**)&att, g_att);
    cudaGetSymbolAddress((void**)&xhi, g_xhi);
    cudaGetSymbolAddress((void**)&xlo, g_xlo);
    cudaGetSymbolAddress((void**)&w1hi, g_w1hi);
    cudaGetSymbolAddress((void**)&w1lo, g_w1lo);
    cudaGetSymbolAddress((void**)&ahi, g_ahi);
    cudaGetSymbolAddress((void**)&alo, g_alo);
    cudaGetSymbolAddress((void**)&w2hi, g_w2hi);
    cudaGetSymbolAddress((void**)&w2lo, g_w2lo);

    cudaFuncSetAttribute(gemm_bf16x3,
                         cudaFuncAttributeMaxDynamicSharedMemorySize, GEMM_SMEM);

    // 0) Split inputs into bf16 hi/lo
    cvt_hilo<<<NPIX * DIM / 1024, 256>>>(x, xhi, xlo);
    cvt_hilo<<<QKVN * DIM / 1024, 256>>>(qkv_w, w1hi, w1lo);
    cvt_hilo<<<DIM * DIM / 1024, 256>>>(proj_w, w2hi, w2lo);

    // 1) QKV projection: [6400,1536] = x @ qkv_w^T + qkv_b
    gemm_bf16x3<<<dim3(QKVN / 128, NPIX / 128), 256, GEMM_SMEM>>>(
        xhi, xlo, w1hi, w1lo, qkv_b, qkv, NPIX, QKVN, DIM);

    // 2) Neighborhood attention
    nat_attn<<<dim3(HWDIM / 8, HWDIM, NHEAD), 256>>>(qkv, rpb, att);

    // 3) Split attention output, then output projection
    cvt_hilo<<<NPIX * DIM / 1024, 256>>>(att, ahi, alo);
    gemm_bf16x3<<<dim3(DIM / 128, NPIX / 128), 256, GEMM_SMEM>>>(
        ahi, alo, w2hi, w2lo, proj_b, out, NPIX, DIM, DIM);
}